// round 11
// baseline (speedup 1.0000x reference)
#include <cuda_runtime.h>
#include <cuda_bf16.h>
#include <cstdint>

#define FH 32
#define FW 88
#define PPC 2816
#define NCAM 6
#define NPIX 16896
#define DD 41
#define CC 64
#define CIN 256
#define NOUT 105
#define NVOX 16384
#define DPAD 44

#define BXX (-50.8f - 0.4f)
#define BYY (-50.8f - 0.4f)
#define BZZ (-10.0f)

typedef unsigned long long ull;

__device__ __align__(16) float g_depth[NPIX * DPAD];
__device__ __align__(16) float g_ctx[NPIX * CC];
__device__ __align__(16) float g_bev[NVOX * CC];
__device__ float g_geo[NCAM][24];
__device__ __align__(16) char g_wtile[4 * 28672];   // per-chunk swizzled bf16 hi+lo

// ---------------------------------------------------------------- helpers
__device__ __forceinline__ void red4(float* addr, float4 v) {
    asm volatile("red.global.add.v4.f32 [%0], {%1,%2,%3,%4};"
                 :: "l"(addr), "f"(v.x), "f"(v.y), "f"(v.z), "f"(v.w) : "memory");
}
__device__ __forceinline__ uint32_t s2u(const void* p) {
    return (uint32_t)__cvta_generic_to_shared(p);
}
__device__ __forceinline__ void cp16(uint32_t s, const void* g) {
    asm volatile("cp.async.ca.shared.global [%0], [%1], 16;" :: "r"(s), "l"(g));
}
__device__ __forceinline__ uint32_t bfpack(float hi, float lo) {
    uint32_t d;
    asm("cvt.rn.bf16x2.f32 %0, %1, %2;" : "=r"(d) : "f"(hi), "f"(lo));
    return d;
}
__device__ __forceinline__ void ldsm4(uint32_t r[4], uint32_t addr) {
    asm volatile("ldmatrix.sync.aligned.m8n8.x4.shared.b16 {%0,%1,%2,%3}, [%4];"
                 : "=r"(r[0]), "=r"(r[1]), "=r"(r[2]), "=r"(r[3]) : "r"(addr));
}
__device__ __forceinline__ void ldsm2t(uint32_t r[2], uint32_t addr) {
    asm volatile("ldmatrix.sync.aligned.m8n8.x2.trans.shared.b16 {%0,%1}, [%2];"
                 : "=r"(r[0]), "=r"(r[1]) : "r"(addr));
}
__device__ __forceinline__ void mma16816(float d[4], const uint32_t a[4],
                                         const uint32_t b[2]) {
    asm volatile(
        "mma.sync.aligned.m16n8k16.row.col.f32.bf16.bf16.f32 "
        "{%0,%1,%2,%3}, {%4,%5,%6,%7}, {%8,%9}, {%0,%1,%2,%3};"
        : "+f"(d[0]), "+f"(d[1]), "+f"(d[2]), "+f"(d[3])
        : "r"(a[0]), "r"(a[1]), "r"(a[2]), "r"(a[3]), "r"(b[0]), "r"(b[1]));
}

// ---------------------------------------------------------------- K0: zero bev
__global__ void k_zero() {
    int i = blockIdx.x * blockDim.x + threadIdx.x;
    reinterpret_cast<float4*>(g_bev)[i] = make_float4(0.f, 0.f, 0.f, 0.f);
}

// -------------------------------------------------- 3x3 inverse via adjugate
__device__ __forceinline__ void inv3(const float* m, float* o) {
    float a = m[0], b = m[1], c = m[2];
    float d = m[3], e = m[4], f = m[5];
    float g = m[6], h = m[7], i = m[8];
    float A = (e * i - f * h);
    float B = -(d * i - f * g);
    float Cc = (d * h - e * g);
    float det = a * A + b * B + c * Cc;
    float id = 1.0f / det;
    o[0] = A * id;  o[1] = -(b * i - c * h) * id;  o[2] = (b * f - c * e) * id;
    o[3] = B * id;  o[4] = (a * i - c * g) * id;   o[5] = -(a * f - c * d) * id;
    o[6] = Cc * id; o[7] = -(a * h - b * g) * id;  o[8] = (a * e - b * d) * id;
}

// ------------------------------------------- per-camera geometry constants
__global__ void k_geo(const float* __restrict__ rots,
                      const float* __restrict__ trans,
                      const float* __restrict__ intrins,
                      const float* __restrict__ post_rots,
                      const float* __restrict__ post_trans) {
    int n = threadIdx.x;
    if (n >= NCAM) return;
    float PR[9], Km[9], R[9], IPR[9], IK[9], M[9];
#pragma unroll
    for (int i = 0; i < 9; ++i) {
        PR[i] = post_rots[n * 9 + i];
        Km[i] = intrins[n * 9 + i];
        R[i]  = rots[n * 9 + i];
    }
    inv3(PR, IPR);
    inv3(Km, IK);
#pragma unroll
    for (int i = 0; i < 3; ++i)
#pragma unroll
        for (int j = 0; j < 3; ++j)
            M[i * 3 + j] = R[i * 3 + 0] * IK[0 + j] + R[i * 3 + 1] * IK[3 + j] +
                           R[i * 3 + 2] * IK[6 + j];
    float* G = g_geo[n];
#pragma unroll
    for (int i = 0; i < 9; ++i) { G[i] = IPR[i]; G[9 + i] = M[i]; }
#pragma unroll
    for (int i = 0; i < 3; ++i) {
        G[18 + i] = trans[n * 3 + i];
        G[21 + i] = post_trans[n * 3 + i];
    }
}

// ------------------- precompute swizzled split-bf16 weight tiles (once) -----
__global__ void __launch_bounds__(256) k_wsplit(const float* __restrict__ wd) {
    const int c = blockIdx.x;          // chunk 0..3
    const int tid = threadIdx.x;
    char* dst = g_wtile + c * 28672;
#pragma unroll
    for (int r = 0; r < 7; ++r) {
        int i = tid + 256 * r;         // 0..1791
        int m = i >> 4, kq = i & 15;
        float4 v = (m < NOUT)
            ? *reinterpret_cast<const float4*>(wd + m * CIN + c * 64 + 4 * kq)
            : make_float4(0.f, 0.f, 0.f, 0.f);
        uint32_t h01 = bfpack(v.y, v.x);
        uint32_t h23 = bfpack(v.w, v.z);
        float f0 = __uint_as_float(h01 << 16);
        float f1 = __uint_as_float(h01 & 0xFFFF0000u);
        float f2 = __uint_as_float(h23 << 16);
        float f3 = __uint_as_float(h23 & 0xFFFF0000u);
        uint32_t l01 = bfpack(v.y - f1, v.x - f0);
        uint32_t l23 = bfpack(v.w - f3, v.z - f2);
        uint32_t off = (uint32_t)(m * 128 + ((kq * 8) ^ ((m & 7) << 4)));
        *reinterpret_cast<uint2*>(dst + off) = make_uint2(h01, h23);
        *reinterpret_cast<uint2*>(dst + 14336 + off) = make_uint2(l01, l23);
    }
}

// ====== K1: bf16-split HMMA GEMM, 264 CTAs x 64 px, 2 CTA/SM + softmax =======
#define KC 64
#define WH_OFF 0
#define WL_OFF 14336
#define XH_OFF 28672
#define XL_OFF 36864
#define DYN_SMEM 45056
#define EPI_S 66

__global__ void __launch_bounds__(256, 2) k_feats_mma(const float* __restrict__ x,
                                                      const float* __restrict__ bd) {
    extern __shared__ char smem[];
    const uint32_t su = s2u(smem);
    float (*epi)[EPI_S] = reinterpret_cast<float(*)[EPI_S]>(smem);

    const int tid = threadIdx.x;
    const int wid = tid >> 5;
    const int lane = tid & 31;
    const int m0 = wid * 16;

    const int pix0 = blockIdx.x * 64;
    const int n = pix0 / PPC;
    const int p0 = pix0 - n * PPC;
    const float* xb = x + n * CIN * PPC + p0;

    float acc[8][4];
#pragma unroll
    for (int nt = 0; nt < 8; ++nt)
#pragma unroll
        for (int j = 0; j < 4; ++j) acc[nt][j] = 0.f;

    float4 xpre[4];
    auto load_x = [&](int c) {
        const int kc = c * KC;
#pragma unroll
        for (int r = 0; r < 4; ++r) {
            int i = tid + 256 * r;
            int k = i >> 4, pq = i & 15;
            xpre[r] = *reinterpret_cast<const float4*>(xb + (kc + k) * PPC + 4 * pq);
        }
    };

    auto fill_sts = [&](int c) {
        // w: async copy of precomputed swizzled split tiles (28672 B)
        const char* wsrc = g_wtile + c * 28672;
#pragma unroll
        for (int r = 0; r < 7; ++r) {
            int i = tid + 256 * r;     // 0..1791 uint4 slots
            cp16(su + 16 * i, wsrc + 16 * i);
        }
        asm volatile("cp.async.commit_group;");
        // x: convert from prefetch regs; rows of 64 px = 128B bf16
#pragma unroll
        for (int r = 0; r < 4; ++r) {
            int i = tid + 256 * r;
            int k = i >> 4, pq = i & 15;
            float4 v = xpre[r];
            uint32_t h01 = bfpack(v.y, v.x);
            uint32_t h23 = bfpack(v.w, v.z);
            float f0 = __uint_as_float(h01 << 16);
            float f1 = __uint_as_float(h01 & 0xFFFF0000u);
            float f2 = __uint_as_float(h23 << 16);
            float f3 = __uint_as_float(h23 & 0xFFFF0000u);
            uint32_t l01 = bfpack(v.y - f1, v.x - f0);
            uint32_t l23 = bfpack(v.w - f3, v.z - f2);
            uint32_t off = (uint32_t)(k * 128 + ((pq * 8) ^ ((k & 7) << 4)));
            *reinterpret_cast<uint2*>(smem + XH_OFF + off) = make_uint2(h01, h23);
            *reinterpret_cast<uint2*>(smem + XL_OFF + off) = make_uint2(l01, l23);
        }
        asm volatile("cp.async.wait_group 0;");
    };

    const int mat = lane >> 3, r8 = lane & 7;
    const uint32_t a_row = (uint32_t)(m0 + (mat & 1) * 8 + r8);
    const uint32_t km16 = (uint32_t)((mat >> 1) * 16);
    const uint32_t rx = (uint32_t)(r8 << 4);
    const uint32_t bkr = (uint32_t)(lane & 15);
    const uint32_t bx = (uint32_t)((lane & 7) << 4);

    load_x(0);
    for (int c = 0; c < 4; ++c) {
        fill_sts(c);
        __syncthreads();
        if (c < 3) load_x(c + 1);

        if (wid < 7) {
#pragma unroll
            for (int kt = 0; kt < 4; ++kt) {
                uint32_t ah[4], al[4];
                uint32_t aoff = a_row * 128 + (((uint32_t)(kt * 32) + km16) ^ rx);
                ldsm4(ah, su + WH_OFF + aoff);
                ldsm4(al, su + WL_OFF + aoff);
                uint32_t brow = ((uint32_t)(kt * 16) + bkr) * 128;
#pragma unroll
                for (int nt = 0; nt < 8; ++nt) {
                    uint32_t bh[2], bl[2];
                    uint32_t boff = brow + (((uint32_t)(nt * 16)) ^ bx);
                    ldsm2t(bh, su + XH_OFF + boff);
                    ldsm2t(bl, su + XL_OFF + boff);
                    mma16816(acc[nt], ah, bh);
                    mma16816(acc[nt], al, bh);
                    mma16816(acc[nt], ah, bl);
                }
            }
        }
        __syncthreads();
    }

    if (wid < 7) {
        const int g = lane >> 2, tg = lane & 3;
#pragma unroll
        for (int nt = 0; nt < 8; ++nt) {
            int px = nt * 8 + tg * 2;
            *reinterpret_cast<float2*>(&epi[m0 + g][px]) =
                make_float2(acc[nt][0], acc[nt][1]);
            *reinterpret_cast<float2*>(&epi[m0 + g + 8][px]) =
                make_float2(acc[nt][2], acc[nt][3]);
        }
    }
    __syncthreads();

    if (tid < 64) {
        const int p = tid;
        float lg[DD];
#pragma unroll
        for (int o = 0; o < DD; ++o) lg[o] = epi[o][p] + bd[o];
        float m = lg[0];
#pragma unroll
        for (int o = 1; o < DD; ++o) m = fmaxf(m, lg[o]);
        float sum = 0.f;
#pragma unroll
        for (int o = 0; o < DD; ++o) { lg[o] = expf(lg[o] - m); sum += lg[o]; }
        float inv = 1.0f / sum;
        float e[DPAD];
#pragma unroll
        for (int o = 0; o < DD; ++o) e[o] = lg[o] * inv;
        e[41] = e[42] = e[43] = 0.f;
        float4* dp = reinterpret_cast<float4*>(g_depth + (pix0 + p) * DPAD);
#pragma unroll
        for (int i = 0; i < DPAD / 4; ++i)
            dp[i] = make_float4(e[4 * i], e[4 * i + 1], e[4 * i + 2], e[4 * i + 3]);
    }

#pragma unroll
    for (int i = tid; i < 1024; i += 256) {
        int p = i >> 4, cq = i & 15;
        int cb = DD + 4 * cq;
        float4 v;
        v.x = epi[cb + 0][p] + bd[cb + 0];
        v.y = epi[cb + 1][p] + bd[cb + 1];
        v.z = epi[cb + 2][p] + bd[cb + 2];
        v.w = epi[cb + 3][p] + bd[cb + 3];
        reinterpret_cast<float4*>(g_ctx + (pix0 + p) * CC)[cq] = v;
    }
}

// ---------------- K2: geometry + ballot-compacted half-warp red4 scatter
__global__ void __launch_bounds__(128) k_scatter() {
    __shared__ int   s_rank[4][DD];
    __shared__ float s_w[4][DD];

    const int wl = threadIdx.x >> 5;
    const int gw = (blockIdx.x * 128 + threadIdx.x) >> 5;
    const int lane = threadIdx.x & 31;
    if (gw >= NPIX) return;
    const int n = gw / PPC;
    const int hw = gw - n * PPC;
    const int h = hw / FW;
    const int w = hw - h * FW;

    const float* G = g_geo[n];
    float IPR[9], M[9];
#pragma unroll
    for (int i = 0; i < 9; ++i) { IPR[i] = G[i]; M[i] = G[9 + i]; }
    const float t0 = G[18], t1 = G[19], t2 = G[20];
    const float pt0 = G[21], pt1 = G[22], pt2 = G[23];

    const float xsc = (float)w * (1407.0f / 87.0f);
    const float ysc = (float)h * (511.0f / 31.0f);
    const float q0 = xsc - pt0, q1 = ysc - pt1;

    auto rankOf = [&](float dv) -> int {
        float q2 = dv - pt2;
        float r0 = IPR[0] * q0 + IPR[1] * q1 + IPR[2] * q2;
        float r1 = IPR[3] * q0 + IPR[4] * q1 + IPR[5] * q2;
        float r2 = IPR[6] * q0 + IPR[7] * q1 + IPR[8] * q2;
        float s0 = r0 * r2, s1 = r1 * r2, s2 = r2;
        float px = M[0] * s0 + M[1] * s1 + M[2] * s2 + t0;
        float py = M[3] * s0 + M[4] * s1 + M[5] * s2 + t1;
        float pz = M[6] * s0 + M[7] * s1 + M[8] * s2 + t2;
        int gx = (int)((px - BXX) / 0.8f);
        int gy = (int)((py - BYY) / 0.8f);
        int gz = (int)((pz - BZZ) / 20.0f);
        return gx + gy * 128 + gz * 16384;
    };

    const int rank0 = rankOf(4.0f + (float)lane);
    const int rank1 = (lane < 9) ? rankOf(36.0f + (float)lane) : -1;
    const bool k0 = (unsigned)rank0 < (unsigned)NVOX;
    const bool k1 = (unsigned)rank1 < (unsigned)NVOX;

    const unsigned mm0 = __ballot_sync(0xffffffffu, k0);
    const unsigned mm1 = __ballot_sync(0xffffffffu, k1);
    const int cnt0 = __popc(mm0);
    const int cnt = cnt0 + __popc(mm1);

    if (k0) {
        int ix = __popc(mm0 & ((1u << lane) - 1u));
        s_rank[wl][ix] = rank0;
        s_w[wl][ix] = g_depth[gw * DPAD + lane];
    }
    if (k1) {
        int ix = cnt0 + __popc(mm1 & ((1u << lane) - 1u));
        s_rank[wl][ix] = rank1;
        s_w[wl][ix] = g_depth[gw * DPAD + 32 + lane];
    }
    __syncwarp();

    const int cl = lane & 15;
    const int half = lane >> 4;
    const float4 cx = reinterpret_cast<const float4*>(g_ctx + gw * CC)[cl];
    float* bevc = g_bev + cl * 4;

    for (int it = 0; it < cnt; it += 2) {
        int b = it + half;
        if (b < cnt) {
            int rr = s_rank[wl][b];
            float dw = s_w[wl][b];
            float4 v = make_float4(cx.x * dw, cx.y * dw, cx.z * dw, cx.w * dw);
            red4(bevc + rr * CC, v);
        }
    }
}

// ------------- K3: [voxel][c] -> out[c][voxel]
__global__ void __launch_bounds__(256) k_transpose(float* __restrict__ out) {
    __shared__ float s[CC][65];
    const int v0 = blockIdx.x * 64;
    const int t = threadIdx.x;
#pragma unroll
    for (int i = 0; i < 4; ++i) {
        int idx = t + i * 256;
        int cq = idx & 15, v = idx >> 4;
        float4 val = reinterpret_cast<const float4*>(g_bev)[(v0 + v) * 16 + cq];
        s[4 * cq + 0][v] = val.x;
        s[4 * cq + 1][v] = val.y;
        s[4 * cq + 2][v] = val.z;
        s[4 * cq + 3][v] = val.w;
    }
    __syncthreads();
#pragma unroll
    for (int i = 0; i < 4; ++i) {
        int idx = t + i * 256;
        int c = idx >> 4, wv = idx & 15;
        float4 val = make_float4(s[c][4 * wv + 0], s[c][4 * wv + 1],
                                 s[c][4 * wv + 2], s[c][4 * wv + 3]);
        reinterpret_cast<float4*>(out)[c * (NVOX / 4) + (v0 >> 2) + wv] = val;
    }
}

extern "C" void kernel_launch(void* const* d_in, const int* in_sizes, int n_in,
                              void* d_out, int out_size) {
    const float* x          = (const float*)d_in[0];
    const float* rots       = (const float*)d_in[1];
    const float* trans      = (const float*)d_in[2];
    const float* intrins    = (const float*)d_in[3];
    const float* post_rots  = (const float*)d_in[4];
    const float* post_trans = (const float*)d_in[5];
    const float* w_depth    = (const float*)d_in[6];
    const float* b_depth    = (const float*)d_in[7];
    float* out = (float*)d_out;

    cudaFuncSetAttribute(k_feats_mma, cudaFuncAttributeMaxDynamicSharedMemorySize,
                         DYN_SMEM);

    k_geo<<<1, 32>>>(rots, trans, intrins, post_rots, post_trans);   // 1
    k_zero<<<1024, 256>>>();                                         // 2
    k_wsplit<<<4, 256>>>(w_depth);                                   // 3
    k_feats_mma<<<NPIX / 64, 256, DYN_SMEM>>>(x, b_depth);           // 4 (profiled)
    k_scatter<<<NPIX / 4, 128>>>();                                  // 5
    k_transpose<<<NVOX / 64, 256>>>(out);                            // 6
}

// round 12
// speedup vs baseline: 1.1146x; 1.1146x over previous
#include <cuda_runtime.h>
#include <cuda_bf16.h>
#include <cstdint>

#define FH 32
#define FW 88
#define PPC 2816
#define NCAM 6
#define NPIX 16896
#define DD 41
#define CC 64
#define CIN 256
#define NOUT 105
#define NVOX 16384

#define BXX (-50.8f - 0.4f)
#define BYY (-50.8f - 0.4f)
#define BZZ (-10.0f)

typedef unsigned long long ull;

__device__ __align__(16) float g_bev[NVOX * CC];
__device__ float g_geo[NCAM][24];
__device__ __align__(16) char g_wtile[4 * 28672];   // per-chunk swizzled bf16 hi+lo

// ---------------------------------------------------------------- helpers
__device__ __forceinline__ void red4(float* addr, float4 v) {
    asm volatile("red.global.add.v4.f32 [%0], {%1,%2,%3,%4};"
                 :: "l"(addr), "f"(v.x), "f"(v.y), "f"(v.z), "f"(v.w) : "memory");
}
__device__ __forceinline__ uint32_t s2u(const void* p) {
    return (uint32_t)__cvta_generic_to_shared(p);
}
__device__ __forceinline__ void cp16(uint32_t s, const void* g) {
    asm volatile("cp.async.ca.shared.global [%0], [%1], 16;" :: "r"(s), "l"(g));
}
__device__ __forceinline__ uint32_t bfpack(float hi, float lo) {
    uint32_t d;
    asm("cvt.rn.bf16x2.f32 %0, %1, %2;" : "=r"(d) : "f"(hi), "f"(lo));
    return d;
}
__device__ __forceinline__ void ldsm4(uint32_t r[4], uint32_t addr) {
    asm volatile("ldmatrix.sync.aligned.m8n8.x4.shared.b16 {%0,%1,%2,%3}, [%4];"
                 : "=r"(r[0]), "=r"(r[1]), "=r"(r[2]), "=r"(r[3]) : "r"(addr));
}
__device__ __forceinline__ void ldsm2t(uint32_t r[2], uint32_t addr) {
    asm volatile("ldmatrix.sync.aligned.m8n8.x2.trans.shared.b16 {%0,%1}, [%2];"
                 : "=r"(r[0]), "=r"(r[1]) : "r"(addr));
}
__device__ __forceinline__ void mma16816(float d[4], const uint32_t a[4],
                                         const uint32_t b[2]) {
    asm volatile(
        "mma.sync.aligned.m16n8k16.row.col.f32.bf16.bf16.f32 "
        "{%0,%1,%2,%3}, {%4,%5,%6,%7}, {%8,%9}, {%0,%1,%2,%3};"
        : "+f"(d[0]), "+f"(d[1]), "+f"(d[2]), "+f"(d[3])
        : "r"(a[0]), "r"(a[1]), "r"(a[2]), "r"(a[3]), "r"(b[0]), "r"(b[1]));
}

// ---------------------------------------------------------------- K0: zero bev
__global__ void k_zero() {
    int i = blockIdx.x * blockDim.x + threadIdx.x;
    reinterpret_cast<float4*>(g_bev)[i] = make_float4(0.f, 0.f, 0.f, 0.f);
}

// -------------------------------------------------- 3x3 inverse via adjugate
__device__ __forceinline__ void inv3(const float* m, float* o) {
    float a = m[0], b = m[1], c = m[2];
    float d = m[3], e = m[4], f = m[5];
    float g = m[6], h = m[7], i = m[8];
    float A = (e * i - f * h);
    float B = -(d * i - f * g);
    float Cc = (d * h - e * g);
    float det = a * A + b * B + c * Cc;
    float id = 1.0f / det;
    o[0] = A * id;  o[1] = -(b * i - c * h) * id;  o[2] = (b * f - c * e) * id;
    o[3] = B * id;  o[4] = (a * i - c * g) * id;   o[5] = -(a * f - c * d) * id;
    o[6] = Cc * id; o[7] = -(a * h - b * g) * id;  o[8] = (a * e - b * d) * id;
}

// ------------------------------------------- per-camera geometry constants
__global__ void k_geo(const float* __restrict__ rots,
                      const float* __restrict__ trans,
                      const float* __restrict__ intrins,
                      const float* __restrict__ post_rots,
                      const float* __restrict__ post_trans) {
    int n = threadIdx.x;
    if (n >= NCAM) return;
    float PR[9], Km[9], R[9], IPR[9], IK[9], M[9];
#pragma unroll
    for (int i = 0; i < 9; ++i) {
        PR[i] = post_rots[n * 9 + i];
        Km[i] = intrins[n * 9 + i];
        R[i]  = rots[n * 9 + i];
    }
    inv3(PR, IPR);
    inv3(Km, IK);
#pragma unroll
    for (int i = 0; i < 3; ++i)
#pragma unroll
        for (int j = 0; j < 3; ++j)
            M[i * 3 + j] = R[i * 3 + 0] * IK[0 + j] + R[i * 3 + 1] * IK[3 + j] +
                           R[i * 3 + 2] * IK[6 + j];
    float* G = g_geo[n];
#pragma unroll
    for (int i = 0; i < 9; ++i) { G[i] = IPR[i]; G[9 + i] = M[i]; }
#pragma unroll
    for (int i = 0; i < 3; ++i) {
        G[18 + i] = trans[n * 3 + i];
        G[21 + i] = post_trans[n * 3 + i];
    }
}

// ------------------- precompute swizzled split-bf16 weight tiles (once) -----
__global__ void __launch_bounds__(256) k_wsplit(const float* __restrict__ wd) {
    const int c = blockIdx.x;
    const int tid = threadIdx.x;
    char* dst = g_wtile + c * 28672;
#pragma unroll
    for (int r = 0; r < 7; ++r) {
        int i = tid + 256 * r;
        int m = i >> 4, kq = i & 15;
        float4 v = (m < NOUT)
            ? *reinterpret_cast<const float4*>(wd + m * CIN + c * 64 + 4 * kq)
            : make_float4(0.f, 0.f, 0.f, 0.f);
        uint32_t h01 = bfpack(v.y, v.x);
        uint32_t h23 = bfpack(v.w, v.z);
        float f0 = __uint_as_float(h01 << 16);
        float f1 = __uint_as_float(h01 & 0xFFFF0000u);
        float f2 = __uint_as_float(h23 << 16);
        float f3 = __uint_as_float(h23 & 0xFFFF0000u);
        uint32_t l01 = bfpack(v.y - f1, v.x - f0);
        uint32_t l23 = bfpack(v.w - f3, v.z - f2);
        uint32_t off = (uint32_t)(m * 128 + ((kq * 8) ^ ((m & 7) << 4)));
        *reinterpret_cast<uint2*>(dst + off) = make_uint2(h01, h23);
        *reinterpret_cast<uint2*>(dst + 14336 + off) = make_uint2(l01, l23);
    }
}

// ========== K1 FUSED: bf16-split HMMA GEMM + softmax + voxel scatter ========
#define KC 64
#define WH_OFF 0
#define WL_OFF 14336
#define XH_OFF 28672
#define XL_OFF 36864
#define DYN_SMEM 45056
#define EPI_S 66
#define TBL_OFF 29696      // per-warp compacted (rank, weight) tables

__global__ void __launch_bounds__(256, 2) k_feats_fused(const float* __restrict__ x,
                                                        const float* __restrict__ bd) {
    extern __shared__ char smem[];
    const uint32_t su = s2u(smem);
    float (*epi)[EPI_S] = reinterpret_cast<float(*)[EPI_S]>(smem);

    const int tid = threadIdx.x;
    const int wid = tid >> 5;
    const int lane = tid & 31;
    const int m0 = wid * 16;

    const int pix0 = blockIdx.x * 64;
    const int n = pix0 / PPC;
    const int p0 = pix0 - n * PPC;
    const float* xb = x + n * CIN * PPC + p0;

    float acc[8][4];
#pragma unroll
    for (int nt = 0; nt < 8; ++nt)
#pragma unroll
        for (int j = 0; j < 4; ++j) acc[nt][j] = 0.f;

    float4 xpre[4];
    auto load_x = [&](int c) {
        const int kc = c * KC;
#pragma unroll
        for (int r = 0; r < 4; ++r) {
            int i = tid + 256 * r;
            int k = i >> 4, pq = i & 15;
            xpre[r] = *reinterpret_cast<const float4*>(xb + (kc + k) * PPC + 4 * pq);
        }
    };

    auto fill_sts = [&](int c) {
        const char* wsrc = g_wtile + c * 28672;
#pragma unroll
        for (int r = 0; r < 7; ++r) {
            int i = tid + 256 * r;
            cp16(su + 16 * i, wsrc + 16 * i);
        }
        asm volatile("cp.async.commit_group;");
#pragma unroll
        for (int r = 0; r < 4; ++r) {
            int i = tid + 256 * r;
            int k = i >> 4, pq = i & 15;
            float4 v = xpre[r];
            uint32_t h01 = bfpack(v.y, v.x);
            uint32_t h23 = bfpack(v.w, v.z);
            float f0 = __uint_as_float(h01 << 16);
            float f1 = __uint_as_float(h01 & 0xFFFF0000u);
            float f2 = __uint_as_float(h23 << 16);
            float f3 = __uint_as_float(h23 & 0xFFFF0000u);
            uint32_t l01 = bfpack(v.y - f1, v.x - f0);
            uint32_t l23 = bfpack(v.w - f3, v.z - f2);
            uint32_t off = (uint32_t)(k * 128 + ((pq * 8) ^ ((k & 7) << 4)));
            *reinterpret_cast<uint2*>(smem + XH_OFF + off) = make_uint2(h01, h23);
            *reinterpret_cast<uint2*>(smem + XL_OFF + off) = make_uint2(l01, l23);
        }
        asm volatile("cp.async.wait_group 0;");
    };

    const int mat = lane >> 3, r8 = lane & 7;
    const uint32_t a_row = (uint32_t)(m0 + (mat & 1) * 8 + r8);
    const uint32_t km16 = (uint32_t)((mat >> 1) * 16);
    const uint32_t rx = (uint32_t)(r8 << 4);
    const uint32_t bkr = (uint32_t)(lane & 15);
    const uint32_t bx = (uint32_t)((lane & 7) << 4);

    load_x(0);
    for (int c = 0; c < 4; ++c) {
        fill_sts(c);
        __syncthreads();
        if (c < 3) load_x(c + 1);

        if (wid < 7) {
#pragma unroll
            for (int kt = 0; kt < 4; ++kt) {
                uint32_t ah[4], al[4];
                uint32_t aoff = a_row * 128 + (((uint32_t)(kt * 32) + km16) ^ rx);
                ldsm4(ah, su + WH_OFF + aoff);
                ldsm4(al, su + WL_OFF + aoff);
                uint32_t brow = ((uint32_t)(kt * 16) + bkr) * 128;
#pragma unroll
                for (int nt = 0; nt < 8; ++nt) {
                    uint32_t bh[2], bl[2];
                    uint32_t boff = brow + (((uint32_t)(nt * 16)) ^ bx);
                    ldsm2t(bh, su + XH_OFF + boff);
                    ldsm2t(bl, su + XL_OFF + boff);
                    mma16816(acc[nt], ah, bh);
                    mma16816(acc[nt], al, bh);
                    mma16816(acc[nt], ah, bl);
                }
            }
        }
        __syncthreads();
    }

    // ---- accumulators -> epi[out][pix] (overlays tiles)
    if (wid < 7) {
        const int g = lane >> 2, tg = lane & 3;
#pragma unroll
        for (int nt = 0; nt < 8; ++nt) {
            int px = nt * 8 + tg * 2;
            *reinterpret_cast<float2*>(&epi[m0 + g][px]) =
                make_float2(acc[nt][0], acc[nt][1]);
            *reinterpret_cast<float2*>(&epi[m0 + g + 8][px]) =
                make_float2(acc[nt][2], acc[nt][3]);
        }
    }
    __syncthreads();

    // ---- softmax in place (rows 0..40 become normalized depth)
    if (tid < 64) {
        const int p = tid;
        float lg[DD];
#pragma unroll
        for (int o = 0; o < DD; ++o) lg[o] = epi[o][p] + bd[o];
        float m = lg[0];
#pragma unroll
        for (int o = 1; o < DD; ++o) m = fmaxf(m, lg[o]);
        float sum = 0.f;
#pragma unroll
        for (int o = 0; o < DD; ++o) { lg[o] = expf(lg[o] - m); sum += lg[o]; }
        float inv = 1.0f / sum;
#pragma unroll
        for (int o = 0; o < DD; ++o) epi[o][p] = lg[o] * inv;
    }
    __syncthreads();

    // ---- fused scatter: each warp handles 8 pixels
    const float* G = g_geo[n];
    float IPR[9], M[9];
#pragma unroll
    for (int i = 0; i < 9; ++i) { IPR[i] = G[i]; M[i] = G[9 + i]; }
    const float t0 = G[18], t1 = G[19], t2 = G[20];
    const float pt0 = G[21], pt1 = G[22], pt2 = G[23];

    const int cl = lane & 15;
    const int half = lane >> 4;
    const float bc0 = bd[DD + 4 * cl + 0];
    const float bc1 = bd[DD + 4 * cl + 1];
    const float bc2 = bd[DD + 4 * cl + 2];
    const float bc3 = bd[DD + 4 * cl + 3];

    int* srk  = reinterpret_cast<int*>(smem + TBL_OFF) + wid * 44;
    float* swt = reinterpret_cast<float*>(smem + TBL_OFF + 8 * 44 * 4) + wid * 44;
    float* bevc = g_bev + cl * 4;

    for (int pp = 0; pp < 8; ++pp) {
        const int p = wid * 8 + pp;
        const int hw = p0 + p;
        const int h = hw / FW;
        const int w = hw - h * FW;

        const float xsc = (float)w * (1407.0f / 87.0f);
        const float ysc = (float)h * (511.0f / 31.0f);
        const float q0 = xsc - pt0, q1 = ysc - pt1;

        auto rankOf = [&](float dv) -> int {
            float q2 = dv - pt2;
            float r0 = IPR[0] * q0 + IPR[1] * q1 + IPR[2] * q2;
            float r1 = IPR[3] * q0 + IPR[4] * q1 + IPR[5] * q2;
            float r2 = IPR[6] * q0 + IPR[7] * q1 + IPR[8] * q2;
            float s0 = r0 * r2, s1 = r1 * r2, s2 = r2;
            float px = M[0] * s0 + M[1] * s1 + M[2] * s2 + t0;
            float py = M[3] * s0 + M[4] * s1 + M[5] * s2 + t1;
            float pz = M[6] * s0 + M[7] * s1 + M[8] * s2 + t2;
            int gx = (int)((px - BXX) / 0.8f);
            int gy = (int)((py - BYY) / 0.8f);
            int gz = (int)((pz - BZZ) / 20.0f);
            return gx + gy * 128 + gz * 16384;
        };

        const int rank0 = rankOf(4.0f + (float)lane);
        const int rank1 = (lane < 9) ? rankOf(36.0f + (float)lane) : -1;
        const bool k0 = (unsigned)rank0 < (unsigned)NVOX;
        const bool k1 = (unsigned)rank1 < (unsigned)NVOX;

        const unsigned mm0 = __ballot_sync(0xffffffffu, k0);
        const unsigned mm1 = __ballot_sync(0xffffffffu, k1);
        const int cnt0 = __popc(mm0);
        const int cnt = cnt0 + __popc(mm1);

        if (k0) {
            int ix = __popc(mm0 & ((1u << lane) - 1u));
            srk[ix] = rank0;
            swt[ix] = epi[lane][p];
        }
        if (k1) {
            int ix = cnt0 + __popc(mm1 & ((1u << lane) - 1u));
            srk[ix] = rank1;
            swt[ix] = epi[lane + 32][p];
        }
        __syncwarp();
        if (cnt == 0) continue;

        const float4 cx = make_float4(epi[DD + 4 * cl + 0][p] + bc0,
                                      epi[DD + 4 * cl + 1][p] + bc1,
                                      epi[DD + 4 * cl + 2][p] + bc2,
                                      epi[DD + 4 * cl + 3][p] + bc3);

        for (int it = 0; it < cnt; it += 2) {
            int b = it + half;
            if (b < cnt) {
                int rr = srk[b];
                float dw = swt[b];
                float4 v = make_float4(cx.x * dw, cx.y * dw, cx.z * dw, cx.w * dw);
                red4(bevc + rr * CC, v);
            }
        }
        __syncwarp();
    }
}

// ------------- K3: [voxel][c] -> out[c][voxel]
__global__ void __launch_bounds__(256) k_transpose(float* __restrict__ out) {
    __shared__ float s[CC][65];
    const int v0 = blockIdx.x * 64;
    const int t = threadIdx.x;
#pragma unroll
    for (int i = 0; i < 4; ++i) {
        int idx = t + i * 256;
        int cq = idx & 15, v = idx >> 4;
        float4 val = reinterpret_cast<const float4*>(g_bev)[(v0 + v) * 16 + cq];
        s[4 * cq + 0][v] = val.x;
        s[4 * cq + 1][v] = val.y;
        s[4 * cq + 2][v] = val.z;
        s[4 * cq + 3][v] = val.w;
    }
    __syncthreads();
#pragma unroll
    for (int i = 0; i < 4; ++i) {
        int idx = t + i * 256;
        int c = idx >> 4, wv = idx & 15;
        float4 val = make_float4(s[c][4 * wv + 0], s[c][4 * wv + 1],
                                 s[c][4 * wv + 2], s[c][4 * wv + 3]);
        reinterpret_cast<float4*>(out)[c * (NVOX / 4) + (v0 >> 2) + wv] = val;
    }
}

extern "C" void kernel_launch(void* const* d_in, const int* in_sizes, int n_in,
                              void* d_out, int out_size) {
    const float* x          = (const float*)d_in[0];
    const float* rots       = (const float*)d_in[1];
    const float* trans      = (const float*)d_in[2];
    const float* intrins    = (const float*)d_in[3];
    const float* post_rots  = (const float*)d_in[4];
    const float* post_trans = (const float*)d_in[5];
    const float* w_depth    = (const float*)d_in[6];
    const float* b_depth    = (const float*)d_in[7];
    float* out = (float*)d_out;

    cudaFuncSetAttribute(k_feats_fused, cudaFuncAttributeMaxDynamicSharedMemorySize,
                         DYN_SMEM);

    k_geo<<<1, 32>>>(rots, trans, intrins, post_rots, post_trans);   // 1
    k_zero<<<1024, 256>>>();                                         // 2
    k_wsplit<<<4, 256>>>(w_depth);                                   // 3
    k_feats_fused<<<NPIX / 64, 256, DYN_SMEM>>>(x, b_depth);         // 4 (profiled)
    k_transpose<<<NVOX / 64, 256>>>(out);                            // 5
}

// round 13
// speedup vs baseline: 1.1969x; 1.0738x over previous
#include <cuda_runtime.h>
#include <cuda_bf16.h>
#include <cstdint>

#define FH 32
#define FW 88
#define PPC 2816
#define NCAM 6
#define NPIX 16896
#define DD 41
#define CC 64
#define CIN 256
#define NOUT 105
#define NVOX 16384

#define BXX (-50.8f - 0.4f)
#define BYY (-50.8f - 0.4f)
#define BZZ (-10.0f)

typedef unsigned long long ull;

__device__ __align__(16) float g_bev[NVOX * CC];
__device__ float g_geo[NCAM][24];
__device__ __align__(16) char g_wtile[4 * 28672];   // per-chunk swizzled bf16 hi+lo

// ---------------------------------------------------------------- helpers
__device__ __forceinline__ void red4(float* addr, float4 v) {
    asm volatile("red.global.add.v4.f32 [%0], {%1,%2,%3,%4};"
                 :: "l"(addr), "f"(v.x), "f"(v.y), "f"(v.z), "f"(v.w) : "memory");
}
__device__ __forceinline__ uint32_t s2u(const void* p) {
    return (uint32_t)__cvta_generic_to_shared(p);
}
__device__ __forceinline__ void cp16(uint32_t s, const void* g) {
    asm volatile("cp.async.ca.shared.global [%0], [%1], 16;" :: "r"(s), "l"(g));
}
__device__ __forceinline__ uint32_t bfpack(float hi, float lo) {
    uint32_t d;
    asm("cvt.rn.bf16x2.f32 %0, %1, %2;" : "=r"(d) : "f"(hi), "f"(lo));
    return d;
}
__device__ __forceinline__ void ldsm4(uint32_t r[4], uint32_t addr) {
    asm volatile("ldmatrix.sync.aligned.m8n8.x4.shared.b16 {%0,%1,%2,%3}, [%4];"
                 : "=r"(r[0]), "=r"(r[1]), "=r"(r[2]), "=r"(r[3]) : "r"(addr));
}
__device__ __forceinline__ void ldsm2t(uint32_t r[2], uint32_t addr) {
    asm volatile("ldmatrix.sync.aligned.m8n8.x2.trans.shared.b16 {%0,%1}, [%2];"
                 : "=r"(r[0]), "=r"(r[1]) : "r"(addr));
}
__device__ __forceinline__ void mma16816(float d[4], const uint32_t a[4],
                                         const uint32_t b[2]) {
    asm volatile(
        "mma.sync.aligned.m16n8k16.row.col.f32.bf16.bf16.f32 "
        "{%0,%1,%2,%3}, {%4,%5,%6,%7}, {%8,%9}, {%0,%1,%2,%3};"
        : "+f"(d[0]), "+f"(d[1]), "+f"(d[2]), "+f"(d[3])
        : "r"(a[0]), "r"(a[1]), "r"(a[2]), "r"(a[3]), "r"(b[0]), "r"(b[1]));
}

// ---------------------------------------------------------------- K0: zero bev
__global__ void k_zero() {
    int i = blockIdx.x * blockDim.x + threadIdx.x;
    reinterpret_cast<float4*>(g_bev)[i] = make_float4(0.f, 0.f, 0.f, 0.f);
}

// -------------------------------------------------- 3x3 inverse via adjugate
__device__ __forceinline__ void inv3(const float* m, float* o) {
    float a = m[0], b = m[1], c = m[2];
    float d = m[3], e = m[4], f = m[5];
    float g = m[6], h = m[7], i = m[8];
    float A = (e * i - f * h);
    float B = -(d * i - f * g);
    float Cc = (d * h - e * g);
    float det = a * A + b * B + c * Cc;
    float id = 1.0f / det;
    o[0] = A * id;  o[1] = -(b * i - c * h) * id;  o[2] = (b * f - c * e) * id;
    o[3] = B * id;  o[4] = (a * i - c * g) * id;   o[5] = -(a * f - c * d) * id;
    o[6] = Cc * id; o[7] = -(a * h - b * g) * id;  o[8] = (a * e - b * d) * id;
}

// ------- setup: blocks 0-3 precompute split-bf16 w tiles; block 4 does geo --
__global__ void __launch_bounds__(256) k_setup(const float* __restrict__ wd,
                                               const float* __restrict__ rots,
                                               const float* __restrict__ trans,
                                               const float* __restrict__ intrins,
                                               const float* __restrict__ post_rots,
                                               const float* __restrict__ post_trans) {
    const int tid = threadIdx.x;
    if (blockIdx.x == 4) {
        int n = tid;
        if (n >= NCAM) return;
        float PR[9], Km[9], R[9], IPR[9], IK[9], M[9];
#pragma unroll
        for (int i = 0; i < 9; ++i) {
            PR[i] = post_rots[n * 9 + i];
            Km[i] = intrins[n * 9 + i];
            R[i]  = rots[n * 9 + i];
        }
        inv3(PR, IPR);
        inv3(Km, IK);
#pragma unroll
        for (int i = 0; i < 3; ++i)
#pragma unroll
            for (int j = 0; j < 3; ++j)
                M[i * 3 + j] = R[i * 3 + 0] * IK[0 + j] + R[i * 3 + 1] * IK[3 + j] +
                               R[i * 3 + 2] * IK[6 + j];
        float* G = g_geo[n];
#pragma unroll
        for (int i = 0; i < 9; ++i) { G[i] = IPR[i]; G[9 + i] = M[i]; }
#pragma unroll
        for (int i = 0; i < 3; ++i) {
            G[18 + i] = trans[n * 3 + i];
            G[21 + i] = post_trans[n * 3 + i];
        }
        return;
    }
    const int c = blockIdx.x;
    char* dst = g_wtile + c * 28672;
#pragma unroll
    for (int r = 0; r < 7; ++r) {
        int i = tid + 256 * r;
        int m = i >> 4, kq = i & 15;
        float4 v = (m < NOUT)
            ? *reinterpret_cast<const float4*>(wd + m * CIN + c * 64 + 4 * kq)
            : make_float4(0.f, 0.f, 0.f, 0.f);
        uint32_t h01 = bfpack(v.y, v.x);
        uint32_t h23 = bfpack(v.w, v.z);
        float f0 = __uint_as_float(h01 << 16);
        float f1 = __uint_as_float(h01 & 0xFFFF0000u);
        float f2 = __uint_as_float(h23 << 16);
        float f3 = __uint_as_float(h23 & 0xFFFF0000u);
        uint32_t l01 = bfpack(v.y - f1, v.x - f0);
        uint32_t l23 = bfpack(v.w - f3, v.z - f2);
        uint32_t off = (uint32_t)(m * 128 + ((kq * 8) ^ ((m & 7) << 4)));
        *reinterpret_cast<uint2*>(dst + off) = make_uint2(h01, h23);
        *reinterpret_cast<uint2*>(dst + 14336 + off) = make_uint2(l01, l23);
    }
}

// ========== K1 FUSED: bf16-split HMMA GEMM + softmax + voxel scatter ========
#define KC 64
#define WH_OFF 0
#define WL_OFF 14336
#define XH_OFF 28672
#define XL_OFF 36864
#define DYN_SMEM 45056
#define EPI_S 66
#define TBL_OFF 29696      // per-warp compacted (rank, weight) tables

__global__ void __launch_bounds__(256, 2) k_feats_fused(const float* __restrict__ x,
                                                        const float* __restrict__ bd) {
    extern __shared__ char smem[];
    const uint32_t su = s2u(smem);
    float (*epi)[EPI_S] = reinterpret_cast<float(*)[EPI_S]>(smem);

    const int tid = threadIdx.x;
    const int wid = tid >> 5;
    const int lane = tid & 31;
    const int m0 = wid * 16;

    const int pix0 = blockIdx.x * 64;
    const int n = pix0 / PPC;
    const int p0 = pix0 - n * PPC;
    const float* xb = x + n * CIN * PPC + p0;

    float acc[8][4];
#pragma unroll
    for (int nt = 0; nt < 8; ++nt)
#pragma unroll
        for (int j = 0; j < 4; ++j) acc[nt][j] = 0.f;

    float4 xpre[4];
    auto load_x = [&](int c) {
        const int kc = c * KC;
#pragma unroll
        for (int r = 0; r < 4; ++r) {
            int i = tid + 256 * r;
            int k = i >> 4, pq = i & 15;
            xpre[r] = *reinterpret_cast<const float4*>(xb + (kc + k) * PPC + 4 * pq);
        }
    };

    auto fill_sts = [&](int c) {
        const char* wsrc = g_wtile + c * 28672;
#pragma unroll
        for (int r = 0; r < 7; ++r) {
            int i = tid + 256 * r;
            cp16(su + 16 * i, wsrc + 16 * i);
        }
        asm volatile("cp.async.commit_group;");
#pragma unroll
        for (int r = 0; r < 4; ++r) {
            int i = tid + 256 * r;
            int k = i >> 4, pq = i & 15;
            float4 v = xpre[r];
            uint32_t h01 = bfpack(v.y, v.x);
            uint32_t h23 = bfpack(v.w, v.z);
            float f0 = __uint_as_float(h01 << 16);
            float f1 = __uint_as_float(h01 & 0xFFFF0000u);
            float f2 = __uint_as_float(h23 << 16);
            float f3 = __uint_as_float(h23 & 0xFFFF0000u);
            uint32_t l01 = bfpack(v.y - f1, v.x - f0);
            uint32_t l23 = bfpack(v.w - f3, v.z - f2);
            uint32_t off = (uint32_t)(k * 128 + ((pq * 8) ^ ((k & 7) << 4)));
            *reinterpret_cast<uint2*>(smem + XH_OFF + off) = make_uint2(h01, h23);
            *reinterpret_cast<uint2*>(smem + XL_OFF + off) = make_uint2(l01, l23);
        }
        asm volatile("cp.async.wait_group 0;");
    };

    const int mat = lane >> 3, r8 = lane & 7;
    const uint32_t a_row = (uint32_t)(m0 + (mat & 1) * 8 + r8);
    const uint32_t km16 = (uint32_t)((mat >> 1) * 16);
    const uint32_t rx = (uint32_t)(r8 << 4);
    const uint32_t bkr = (uint32_t)(lane & 15);
    const uint32_t bx = (uint32_t)((lane & 7) << 4);

    load_x(0);
    for (int c = 0; c < 4; ++c) {
        fill_sts(c);
        __syncthreads();
        if (c < 3) load_x(c + 1);

        if (wid < 7) {
#pragma unroll
            for (int kt = 0; kt < 4; ++kt) {
                uint32_t ah[4], al[4];
                uint32_t aoff = a_row * 128 + (((uint32_t)(kt * 32) + km16) ^ rx);
                ldsm4(ah, su + WH_OFF + aoff);
                ldsm4(al, su + WL_OFF + aoff);
                uint32_t brow = ((uint32_t)(kt * 16) + bkr) * 128;
#pragma unroll
                for (int np = 0; np < 4; ++np) {
                    uint32_t bh0[2], bl0[2], bh1[2], bl1[2];
                    uint32_t bo0 = brow + (((uint32_t)(np * 32)) ^ bx);
                    uint32_t bo1 = brow + (((uint32_t)(np * 32 + 16)) ^ bx);
                    ldsm2t(bh0, su + XH_OFF + bo0);
                    ldsm2t(bh1, su + XH_OFF + bo1);
                    ldsm2t(bl0, su + XL_OFF + bo0);
                    ldsm2t(bl1, su + XL_OFF + bo1);
                    const int n0 = np * 2, n1 = np * 2 + 1;
                    // interleaved passes: >=1 independent MMA between RAW pairs
                    mma16816(acc[n0], ah, bh0);
                    mma16816(acc[n1], ah, bh1);
                    mma16816(acc[n0], al, bh0);
                    mma16816(acc[n1], al, bh1);
                    mma16816(acc[n0], ah, bl0);
                    mma16816(acc[n1], ah, bl1);
                }
            }
        }
        __syncthreads();
    }

    // ---- accumulators -> epi[out][pix] (overlays tiles)
    if (wid < 7) {
        const int g = lane >> 2, tg = lane & 3;
#pragma unroll
        for (int nt = 0; nt < 8; ++nt) {
            int px = nt * 8 + tg * 2;
            *reinterpret_cast<float2*>(&epi[m0 + g][px]) =
                make_float2(acc[nt][0], acc[nt][1]);
            *reinterpret_cast<float2*>(&epi[m0 + g + 8][px]) =
                make_float2(acc[nt][2], acc[nt][3]);
        }
    }
    __syncthreads();

    // ---- softmax in place (rows 0..40 become normalized depth)
    if (tid < 64) {
        const int p = tid;
        float lg[DD];
#pragma unroll
        for (int o = 0; o < DD; ++o) lg[o] = epi[o][p] + bd[o];
        float m = lg[0];
#pragma unroll
        for (int o = 1; o < DD; ++o) m = fmaxf(m, lg[o]);
        float sum = 0.f;
#pragma unroll
        for (int o = 0; o < DD; ++o) { lg[o] = expf(lg[o] - m); sum += lg[o]; }
        float inv = 1.0f / sum;
#pragma unroll
        for (int o = 0; o < DD; ++o) epi[o][p] = lg[o] * inv;
    }
    __syncthreads();

    // ---- fused scatter: each warp handles 8 pixels
    const float* G = g_geo[n];
    float IPR[9], M[9];
#pragma unroll
    for (int i = 0; i < 9; ++i) { IPR[i] = G[i]; M[i] = G[9 + i]; }
    const float t0 = G[18], t1 = G[19], t2 = G[20];
    const float pt0 = G[21], pt1 = G[22], pt2 = G[23];

    const int cl = lane & 15;
    const int half = lane >> 4;
    const float bc0 = bd[DD + 4 * cl + 0];
    const float bc1 = bd[DD + 4 * cl + 1];
    const float bc2 = bd[DD + 4 * cl + 2];
    const float bc3 = bd[DD + 4 * cl + 3];

    int* srk  = reinterpret_cast<int*>(smem + TBL_OFF) + wid * 44;
    float* swt = reinterpret_cast<float*>(smem + TBL_OFF + 8 * 44 * 4) + wid * 44;
    float* bevc = g_bev + cl * 4;

    for (int pp = 0; pp < 8; ++pp) {
        const int p = wid * 8 + pp;
        const int hw = p0 + p;
        const int h = hw / FW;
        const int w = hw - h * FW;

        const float xsc = (float)w * (1407.0f / 87.0f);
        const float ysc = (float)h * (511.0f / 31.0f);
        const float q0 = xsc - pt0, q1 = ysc - pt1;

        auto rankOf = [&](float dv) -> int {
            float q2 = dv - pt2;
            float r0 = IPR[0] * q0 + IPR[1] * q1 + IPR[2] * q2;
            float r1 = IPR[3] * q0 + IPR[4] * q1 + IPR[5] * q2;
            float r2 = IPR[6] * q0 + IPR[7] * q1 + IPR[8] * q2;
            float s0 = r0 * r2, s1 = r1 * r2, s2 = r2;
            float px = M[0] * s0 + M[1] * s1 + M[2] * s2 + t0;
            float py = M[3] * s0 + M[4] * s1 + M[5] * s2 + t1;
            float pz = M[6] * s0 + M[7] * s1 + M[8] * s2 + t2;
            int gx = (int)((px - BXX) / 0.8f);
            int gy = (int)((py - BYY) / 0.8f);
            int gz = (int)((pz - BZZ) / 20.0f);
            return gx + gy * 128 + gz * 16384;
        };

        const int rank0 = rankOf(4.0f + (float)lane);
        const int rank1 = (lane < 9) ? rankOf(36.0f + (float)lane) : -1;
        const bool k0 = (unsigned)rank0 < (unsigned)NVOX;
        const bool k1 = (unsigned)rank1 < (unsigned)NVOX;

        const unsigned mm0 = __ballot_sync(0xffffffffu, k0);
        const unsigned mm1 = __ballot_sync(0xffffffffu, k1);
        const int cnt0 = __popc(mm0);
        const int cnt = cnt0 + __popc(mm1);

        if (k0) {
            int ix = __popc(mm0 & ((1u << lane) - 1u));
            srk[ix] = rank0;
            swt[ix] = epi[lane][p];
        }
        if (k1) {
            int ix = cnt0 + __popc(mm1 & ((1u << lane) - 1u));
            srk[ix] = rank1;
            swt[ix] = epi[lane + 32][p];
        }
        __syncwarp();
        if (cnt == 0) continue;

        const float4 cx = make_float4(epi[DD + 4 * cl + 0][p] + bc0,
                                      epi[DD + 4 * cl + 1][p] + bc1,
                                      epi[DD + 4 * cl + 2][p] + bc2,
                                      epi[DD + 4 * cl + 3][p] + bc3);

        for (int it = 0; it < cnt; it += 2) {
            int b = it + half;
            if (b < cnt) {
                int rr = srk[b];
                float dw = swt[b];
                float4 v = make_float4(cx.x * dw, cx.y * dw, cx.z * dw, cx.w * dw);
                red4(bevc + rr * CC, v);
            }
        }
        __syncwarp();
    }
}

// ------------- K3: [voxel][c] -> out[c][voxel], 16 vox/CTA, 1024 CTAs
__global__ void __launch_bounds__(256) k_transpose(float* __restrict__ out) {
    __shared__ float s[CC][17];
    const int v0 = blockIdx.x * 16;
    const int t = threadIdx.x;
    {
        int cq = t & 15, v = t >> 4;
        float4 val = reinterpret_cast<const float4*>(g_bev)[(v0 + v) * 16 + cq];
        s[4 * cq + 0][v] = val.x;
        s[4 * cq + 1][v] = val.y;
        s[4 * cq + 2][v] = val.z;
        s[4 * cq + 3][v] = val.w;
    }
    __syncthreads();
    {
        int c = t >> 2, wv = t & 3;
        float4 val = make_float4(s[c][4 * wv + 0], s[c][4 * wv + 1],
                                 s[c][4 * wv + 2], s[c][4 * wv + 3]);
        reinterpret_cast<float4*>(out)[c * (NVOX / 4) + (v0 >> 2) + wv] = val;
    }
}

extern "C" void kernel_launch(void* const* d_in, const int* in_sizes, int n_in,
                              void* d_out, int out_size) {
    const float* x          = (const float*)d_in[0];
    const float* rots       = (const float*)d_in[1];
    const float* trans      = (const float*)d_in[2];
    const float* intrins    = (const float*)d_in[3];
    const float* post_rots  = (const float*)d_in[4];
    const float* post_trans = (const float*)d_in[5];
    const float* w_depth    = (const float*)d_in[6];
    const float* b_depth    = (const float*)d_in[7];
    float* out = (float*)d_out;

    cudaFuncSetAttribute(k_feats_fused, cudaFuncAttributeMaxDynamicSharedMemorySize,
                         DYN_SMEM);

    k_zero<<<1024, 256>>>();                                          // 1
    k_setup<<<5, 256>>>(w_depth, rots, trans, intrins, post_rots,
                        post_trans);                                  // 2
    k_nopPlaceholder:;
    k_feats_fused<<<NPIX / 64, 256, DYN_SMEM>>>(x, b_depth);          // 3
    k_feats_fused_done:;
    k_transpose<<<NVOX / 16, 256>>>(out);                             // 4
}